// round 6
// baseline (speedup 1.0000x reference)
#include <cuda_runtime.h>

// LookupFreeQuantizer — sm_103a, round 5: single fused kernel, hoisted fences.
// Factorized softmax: p(bit_c=+1) = sigmoid(400 z_c).
//   per_sample_entropy = sum_c BinaryEntropy  (exact)
//   probs[n] = P0 * prod_{c in flipset} e_c,  e_c = exp(-400|z_c|), P0 = prod 1/(1+e_c)
// Sparse scatter: only subsets with e_c > 1e-7 carry mass > 1e-7
// (neglected mass <= 1e-6/sample -> avg_entropy abs err ~1e-5, << 1e-3 gate).
// Output layout (fp32): [ z_q 655360 | loss, commit, ent_loss, pse, avg_ent | indices 65536 ]

#define CH      10
#define HW      1024
#define NSAMP   65536
#define OUT_SCALARS 655360
#define OUT_IDX     655365
#define THRESH  1e-7f
#define NBLK    256
#define NTHR    256

// Zero-initialized at load; last block re-zeroes after use -> graph-replay safe.
__device__ float        g_avg[1024];
__device__ double       g_ent;
__device__ double       g_commit;
__device__ unsigned int g_count;

__global__ void __launch_bounds__(NTHR)
fused_kernel(const float* __restrict__ z, float* __restrict__ out) {
    __shared__ float bins[1024];
    __shared__ float we[8], wc[8];
    __shared__ bool  isLast;

    const int tid  = threadIdx.x;
    const int lane = tid & 31;
    const int wrp  = tid >> 5;
    const int s    = blockIdx.x * NTHR + tid;      // one sample per thread

    #pragma unroll
    for (int k = 0; k < 4; k++) bins[tid + k * 256] = 0.f;
    __syncthreads();

    // ---- per-sample math ----
    const int base = (s >> 10) * (CH * HW) + (s & (HW - 1));
    const float* zp = z + base;
    float* op = out + base;

    float eloc[CH];
    float P0 = 1.f, Hs = 0.f, comAcc = 0.f;
    int idx = 0;
    unsigned m = 0;

    #pragma unroll
    for (int c = 0; c < CH; c++) {
        float v = zp[c * HW];                      // coalesced
        bool pos = v > 0.f;
        float sgn = pos ? 1.f : -1.f;
        op[c * HW] = sgn;                          // z_q
        float d = sgn - v;
        comAcc = fmaf(d, d, comAcc);
        float a = 400.f * fabsf(v);
        float ec = __expf(-a);
        eloc[c] = ec;
        float pmaj, H;
        if (ec > THRESH) {                         // rare (~3%/channel)
            pmaj = __fdividef(1.f, 1.f + ec);
            H = log1pf(ec) + a * ec * pmaj;        // exact binary entropy
            m |= (1u << c);
        } else {
            pmaj = 1.f - ec;
            H = ec * (1.f + a);                    // 1st-order, err < 1e-12
        }
        P0 *= pmaj;
        Hs += H;
        if (pos) idx |= (1 << c);
    }
    out[OUT_IDX + s] = (float)idx;

    // ---- sparse prob scatter into shared histogram ----
    unsigned sub = m;
    for (;;) {
        float w = P0;
        unsigned tt = sub;
        while (tt) {
            int c = __ffs(tt) - 1;
            tt &= tt - 1;
            w *= eloc[c];
        }
        atomicAdd(&bins[idx ^ (int)sub], w);
        if (!sub) break;
        sub = (sub - 1) & m;
    }

    // ---- block reduce entropy + commitment ----
    float entAcc = Hs;
    #pragma unroll
    for (int o = 16; o; o >>= 1) {
        entAcc += __shfl_down_sync(0xffffffffu, entAcc, o);
        comAcc += __shfl_down_sync(0xffffffffu, comAcc, o);
    }
    if (lane == 0) { we[wrp] = entAcc; wc[wrp] = comAcc; }
    __syncthreads();
    if (wrp == 0) {
        float e2 = (lane < 8) ? we[lane] : 0.f;
        float c2 = (lane < 8) ? wc[lane] : 0.f;
        #pragma unroll
        for (int o = 4; o; o >>= 1) {
            e2 += __shfl_down_sync(0xffffffffu, e2, o);
            c2 += __shfl_down_sync(0xffffffffu, c2, o);
        }
        if (lane == 0) {
            atomicAdd(&g_ent, (double)e2);
            atomicAdd(&g_commit, (double)c2);
        }
    }

    // ---- drain nonzero bins to global (RED.F32, no return) ----
    #pragma unroll
    for (int k = 0; k < 4; k++) {
        float v = bins[tid + k * 256];
        if (v != 0.f) atomicAdd(&g_avg[tid + k * 256], v);
    }

    // ---- hoisted-fence arrival: bar.sync (CTA order) + ONE gpu fence by tid0 ----
    __syncthreads();
    if (tid == 0) {
        asm volatile("fence.acq_rel.gpu;" ::: "memory");   // release all block's REDs
        isLast = (atomicAdd(&g_count, 1u) == (unsigned)(gridDim.x - 1));
    }
    __syncthreads();
    if (!isLast) return;
    if (tid == 0)
        asm volatile("fence.acq_rel.gpu;" ::: "memory");   // acquire others' REDs
    __syncthreads();

    // ---- last-block finalize ----
    float term = 0.f;
    #pragma unroll
    for (int k = 0; k < 4; k++) {
        float p = __ldcg(&g_avg[tid + k * 256]) * (1.f / 65536.f);
        term = fmaf(p, __logf(p + 1e-5f), term);
    }
    #pragma unroll
    for (int o = 16; o; o >>= 1) term += __shfl_down_sync(0xffffffffu, term, o);
    if (lane == 0) we[wrp] = term;
    __syncthreads();
    if (tid < 32) {
        float v = (tid < 8) ? we[tid] : 0.f;
        #pragma unroll
        for (int o = 4; o; o >>= 1) v += __shfl_down_sync(0xffffffffu, v, o);
        if (tid == 0) {
            double ent_d = __ldcg(&g_ent);
            double com_d = __ldcg(&g_commit);
            float pse          = (float)(ent_d / 65536.0);
            float avg_entropy  = -v;                        // ENT_GAMMA = 1.0
            float entropy_loss = 0.1f * (pse - avg_entropy);
            float commitment   = 0.25f * (float)(com_d / 655360.0);
            out[OUT_SCALARS + 0] = commitment + entropy_loss;  // loss
            out[OUT_SCALARS + 1] = commitment;
            out[OUT_SCALARS + 2] = entropy_loss;
            out[OUT_SCALARS + 3] = pse;
            out[OUT_SCALARS + 4] = avg_entropy;
            g_ent = 0.0;
            g_commit = 0.0;
            g_count = 0u;
        }
    }
    // reset g_avg for the next (graph-replayed) launch
    __syncthreads();
    #pragma unroll
    for (int k = 0; k < 4; k++) g_avg[tid + k * 256] = 0.f;
}

extern "C" void kernel_launch(void* const* d_in, const int* in_sizes, int n_in,
                              void* d_out, int out_size) {
    const float* z = (const float*)d_in[0];
    float* out = (float*)d_out;
    fused_kernel<<<NBLK, NTHR>>>(z, out);
}

// round 7
// speedup vs baseline: 1.2041x; 1.2041x over previous
#include <cuda_runtime.h>

// LookupFreeQuantizer — sm_103a, round 6: fused kernel, float4 x4 samples/thread,
// register-only subset products, branchless entropy.
// Factorized softmax: p(bit_c=+1) = sigmoid(400 z_c).
//   per_sample_entropy = sum_c [ log(1+e_c) + a_c e_c/(1+e_c) ],  e_c = exp(-400|z_c|)
//   probs[n] = P0 * prod_{c in flipset} e_c,  P0 = prod 1/(1+e_c)
// Sparse scatter: only subsets with e_c > 1e-7 carry mass > 1e-7
// (neglected mass <= 1e-6/sample -> avg_entropy abs err ~1e-5, << 1e-3 gate).
// Output layout (fp32): [ z_q 655360 | loss, commit, ent_loss, pse, avg_ent | indices 65536 ]

#define CH      10
#define HW      1024
#define OUT_SCALARS 655360
#define OUT_IDX     655365
#define THRESH  1e-7f
#define NBLK    64
#define NTHR    256

// Zero-initialized at load; last block re-zeroes after use -> graph-replay safe.
__device__ float        g_avg[1024];
__device__ float        g_ent;
__device__ float        g_commit;
__device__ unsigned int g_count;

__global__ void __launch_bounds__(NTHR)
fused_kernel(const float* __restrict__ z, float* __restrict__ out) {
    __shared__ float bins[1024];
    __shared__ float we[8], wc[8];
    __shared__ bool  isLast;

    const int tid  = threadIdx.x;
    const int lane = tid & 31;
    const int wrp  = tid >> 5;
    const int s    = (blockIdx.x * NTHR + tid) * 4;    // 4 consecutive samples

    #pragma unroll
    for (int k = 0; k < 4; k++) bins[tid + k * 256] = 0.f;
    __syncthreads();

    // ---- vectorized load: 4 samples x 10 channels ----
    const int base = (s >> 10) * (CH * HW) + (s & (HW - 1));   // 4-aligned
    const float4* zp = (const float4*)(z + base);
    float4* op = (float4*)(out + base);

    float4 v4[CH];
    #pragma unroll
    for (int c = 0; c < CH; c++) v4[c] = zp[c * (HW / 4)];

    // ---- z_q (sign) store + commitment, vectorized ----
    float comAcc = 0.f;
    #pragma unroll
    for (int c = 0; c < CH; c++) {
        float4 v = v4[c], sg;
        sg.x = v.x > 0.f ? 1.f : -1.f;
        sg.y = v.y > 0.f ? 1.f : -1.f;
        sg.z = v.z > 0.f ? 1.f : -1.f;
        sg.w = v.w > 0.f ? 1.f : -1.f;
        op[c * (HW / 4)] = sg;
        float dx = sg.x - v.x, dy = sg.y - v.y, dz = sg.z - v.z, dw = sg.w - v.w;
        comAcc = fmaf(dx, dx, comAcc);
        comAcc = fmaf(dy, dy, comAcc);
        comAcc = fmaf(dz, dz, comAcc);
        comAcc = fmaf(dw, dw, comAcc);
    }

    // ---- per-sample entropy + index + sparse prob scatter ----
    float entAcc = 0.f;
    #pragma unroll
    for (int j = 0; j < 4; j++) {
        float el[CH];                       // fully unrolled -> registers
        float P0 = 1.f;
        int idx = 0;
        unsigned m = 0;
        #pragma unroll
        for (int c = 0; c < CH; c++) {
            float v = (j == 0) ? v4[c].x : (j == 1) ? v4[c].y
                    : (j == 2) ? v4[c].z : v4[c].w;
            float a  = 400.f * fabsf(v);
            float ec = __expf(-a);
            el[c] = ec;
            float pmaj = __fdividef(1.f, 1.f + ec);      // MUFU.RCP
            entAcc += __logf(1.f + ec) + a * ec * pmaj;  // branchless exact-enough H
            P0 *= pmaj;
            if (ec > THRESH) m |= (1u << c);
            if (v > 0.f)     idx |= (1 << c);
        }
        out[OUT_IDX + s + j] = (float)idx;

        atomicAdd(&bins[idx], P0);                       // empty flipset (71% only this)
        unsigned sub = m;
        while (sub) {                                    // rare nonzero submasks
            float w = P0;
            #pragma unroll
            for (int c = 0; c < CH; c++)
                if (sub & (1u << c)) w *= el[c];         // predicated FMUL, const index
            atomicAdd(&bins[idx ^ (int)sub], w);
            sub = (sub - 1) & m;
        }
    }

    // ---- block reduce entropy + commitment ----
    #pragma unroll
    for (int o = 16; o; o >>= 1) {
        entAcc += __shfl_down_sync(0xffffffffu, entAcc, o);
        comAcc += __shfl_down_sync(0xffffffffu, comAcc, o);
    }
    if (lane == 0) { we[wrp] = entAcc; wc[wrp] = comAcc; }
    __syncthreads();
    if (wrp == 0) {
        float e2 = (lane < 8) ? we[lane] : 0.f;
        float c2 = (lane < 8) ? wc[lane] : 0.f;
        #pragma unroll
        for (int o = 4; o; o >>= 1) {
            e2 += __shfl_down_sync(0xffffffffu, e2, o);
            c2 += __shfl_down_sync(0xffffffffu, c2, o);
        }
        if (lane == 0) {
            atomicAdd(&g_ent, e2);
            atomicAdd(&g_commit, c2);
        }
    }

    // ---- drain nonzero bins to global (RED.F32) ----
    #pragma unroll
    for (int k = 0; k < 4; k++) {
        float v = bins[tid + k * 256];
        if (v != 0.f) atomicAdd(&g_avg[tid + k * 256], v);
    }

    // ---- arrival: bar.sync (CTA order) + one gpu fence by tid0 ----
    __syncthreads();
    if (tid == 0) {
        asm volatile("fence.acq_rel.gpu;" ::: "memory");  // release this block's REDs
        isLast = (atomicAdd(&g_count, 1u) == (unsigned)(gridDim.x - 1));
    }
    __syncthreads();
    if (!isLast) return;
    if (tid == 0)
        asm volatile("fence.acq_rel.gpu;" ::: "memory");  // acquire others' REDs
    __syncthreads();

    // ---- last-block finalize ----
    float term = 0.f;
    #pragma unroll
    for (int k = 0; k < 4; k++) {
        float p = __ldcg(&g_avg[tid + k * 256]) * (1.f / 65536.f);
        term = fmaf(p, __logf(p + 1e-5f), term);
    }
    #pragma unroll
    for (int o = 16; o; o >>= 1) term += __shfl_down_sync(0xffffffffu, term, o);
    if (lane == 0) we[wrp] = term;
    __syncthreads();
    if (tid < 32) {
        float v = (tid < 8) ? we[tid] : 0.f;
        #pragma unroll
        for (int o = 4; o; o >>= 1) v += __shfl_down_sync(0xffffffffu, v, o);
        if (tid == 0) {
            float pse          = __ldcg(&g_ent) * (1.f / 65536.f);
            float avg_entropy  = -v;                        // ENT_GAMMA = 1.0
            float entropy_loss = 0.1f * (pse - avg_entropy);
            float commitment   = 0.25f * (__ldcg(&g_commit) * (1.f / 655360.f));
            out[OUT_SCALARS + 0] = commitment + entropy_loss;  // loss
            out[OUT_SCALARS + 1] = commitment;
            out[OUT_SCALARS + 2] = entropy_loss;
            out[OUT_SCALARS + 3] = pse;
            out[OUT_SCALARS + 4] = avg_entropy;
            g_ent = 0.f;
            g_commit = 0.f;
            g_count = 0u;
        }
    }
    // reset g_avg for the next (graph-replayed) launch
    __syncthreads();
    #pragma unroll
    for (int k = 0; k < 4; k++) g_avg[tid + k * 256] = 0.f;
}

extern "C" void kernel_launch(void* const* d_in, const int* in_sizes, int n_in,
                              void* d_out, int out_size) {
    const float* z = (const float*)d_in[0];
    float* out = (float*)d_out;
    fused_kernel<<<NBLK, NTHR>>>(z, out);
}